// round 16
// baseline (speedup 1.0000x reference)
#include <cuda_runtime.h>
#include <cstdint>

#define BATCH     512
#define NP        256
#define BOND      128
#define RANK      64
#define EMB       512

// packed fp32x2 helpers ------------------------------------------------------
#define FMA2(d, a, b) \
    asm("fma.rn.f32x2 %0, %1, %2, %0;" : "+l"(d) : "l"(a), "l"(b))
#define BCAST2(d, s) \
    asm("mov.b64 %0, {%1, %1};" : "=l"(d) : "r"(__float_as_uint(s)))
#define PACK2(d, lo, hi) \
    asm("mov.b64 %0, {%1, %2};" : "=l"(d) : "r"(__float_as_uint(lo)), "r"(__float_as_uint(hi)))
#define UNPK2(lo, hi, s) \
    asm("mov.b64 {%0, %1}, %2;" : "=r"(lo), "=r"(hi) : "l"(s))

// cp.async helpers -----------------------------------------------------------
__device__ __forceinline__ void cp_async16(void* dst, const void* src) {
    unsigned sa = (unsigned)__cvta_generic_to_shared(dst);
    asm volatile("cp.async.ca.shared.global [%0], [%1], 16;\n" :: "r"(sa), "l"(src));
}
#define CP_COMMIT() asm volatile("cp.async.commit_group;\n" ::: "memory")
#define CP_WAIT0()  asm volatile("cp.async.wait_group 0;\n" ::: "memory")
#define CP_WAIT1()  asm volatile("cp.async.wait_group 1;\n" ::: "memory")

// ---------------- scratch (static device globals: allocation-free) ----------
__device__ float g_h0[BATCH * NP * BOND];   // 67 MB
__device__ float g_h1[BATCH * 64 * BOND];
__device__ float g_h2[BATCH * 16 * BOND];

// ============================================================================
// K1: patchify + patch GEMM + bias + pos (unchanged, passing)
// ============================================================================
__global__ void __launch_bounds__(256)
patch_embed_kernel(const float* __restrict__ x,
                   const float* __restrict__ Wp,
                   const float* __restrict__ bp,
                   const float* __restrict__ pos)
{
    extern __shared__ float sm[];
    float* At = sm;                 // [64][132]  (k-major)
    float* Ws = sm + 64 * 132;      // [64][128]

    const int tid = threadIdx.x;
    const int r0  = blockIdx.x * 128;

    for (int idx = tid; idx < 128 * 64; idx += 256) {
        int i = idx >> 6;
        int k = idx & 63;
        int row = r0 + i;
        int b = row >> 8, p = row & 255;
        int gy = p >> 4, gx = p & 15;
        int py = k >> 3, px = k & 7;
        At[k * 132 + i] = x[(b * 128 + gy * 8 + py) * 128 + gx * 8 + px];
    }
    for (int idx = tid; idx < 64 * 128; idx += 256)
        Ws[idx] = Wp[idx];
    __syncthreads();

    const int rg = tid >> 4;
    const int cg = tid & 15;

    unsigned long long acc2[8][4];
#pragma unroll
    for (int j = 0; j < 8; j++)
#pragma unroll
        for (int i = 0; i < 4; i++) acc2[j][i] = 0ULL;

#pragma unroll 4
    for (int k = 0; k < 64; k++) {
        ulonglong2 w01 = *(const ulonglong2*)(Ws + k * 128 + cg * 8);
        ulonglong2 w23 = *(const ulonglong2*)(Ws + k * 128 + cg * 8 + 4);
        float4 a0 = *(const float4*)(At + k * 132 + rg * 8);
        float4 a1 = *(const float4*)(At + k * 132 + rg * 8 + 4);
        float a[8] = {a0.x, a0.y, a0.z, a0.w, a1.x, a1.y, a1.z, a1.w};
#pragma unroll
        for (int j = 0; j < 8; j++) {
            unsigned long long aa;
            BCAST2(aa, a[j]);
            FMA2(acc2[j][0], aa, w01.x);
            FMA2(acc2[j][1], aa, w01.y);
            FMA2(acc2[j][2], aa, w23.x);
            FMA2(acc2[j][3], aa, w23.y);
        }
    }

    float4 bp0 = *(const float4*)(bp + cg * 8);
    float4 bp1 = *(const float4*)(bp + cg * 8 + 4);
#pragma unroll
    for (int j = 0; j < 8; j++) {
        int row = r0 + rg * 8 + j;
        int p = row & 255;
        float4 p0 = *(const float4*)(pos + p * 128 + cg * 8);
        float4 p1 = *(const float4*)(pos + p * 128 + cg * 8 + 4);
        unsigned v[8];
#pragma unroll
        for (int i = 0; i < 4; i++) UNPK2(v[2 * i], v[2 * i + 1], acc2[j][i]);
        float4 o0, o1;
        o0.x = __uint_as_float(v[0]) + bp0.x + p0.x;
        o0.y = __uint_as_float(v[1]) + bp0.y + p0.y;
        o0.z = __uint_as_float(v[2]) + bp0.z + p0.z;
        o0.w = __uint_as_float(v[3]) + bp0.w + p0.w;
        o1.x = __uint_as_float(v[4]) + bp1.x + p1.x;
        o1.y = __uint_as_float(v[5]) + bp1.y + p1.y;
        o1.z = __uint_as_float(v[6]) + bp1.z + p1.z;
        o1.w = __uint_as_float(v[7]) + bp1.w + p1.w;
        *(float4*)(g_h0 + (size_t)row * 128 + cg * 8)     = o0;
        *(float4*)(g_h0 + (size_t)row * 128 + cg * 8 + 4) = o1;
    }
}

// ============================================================================
// K2 v4: CP level for L0/L1 (TB=32). cp.async double-buffered F (CK=16),
//   async O prefetch under the U/P epilogue.
// ============================================================================
__global__ void __launch_bounds__(256)
cp_level_v4(const float* __restrict__ in,
            float* __restrict__ out,
            const float* __restrict__ f,
            const float* __restrict__ o,
            int g)
{
    constexpr int TB = 32;
    constexpr int XS = 36;           // Xt row stride (mult of 4)
    constexpr int CK = 16;           // F k-chunk
    constexpr int NCH = 128 / CK;    // 8 chunks

    extern __shared__ float sm[];
    float* Xt = sm;                        // [4][128][36] = 18432 floats
    float* Fs = sm + 4 * 128 * XS;         // [2][4][CK][64] = 8192 floats
    float* Us = sm;                        // alias Xt: [4][32][68] = 8704
    float* Ps = sm + 4 * TB * 68;          // alias Xt+8704: [32][68] = 2176
    float* Os = Fs;                        // alias Fs: [64][128] = 8192 floats

    const int t  = threadIdx.x;
    const int q  = t >> 6;
    const int tg = t & 63;
    const int bg = tg >> 4;          // 0..3 -> rows bg*8..
    const int rg = tg & 15;          // ranks rg*4..+3

    const int node = blockIdx.y;
    const int b0   = blockIdx.x * TB;
    const int g2   = g >> 1;
    const int ny   = node / g2, nx = node % g2;
    const size_t inStride  = (size_t)g * g * BOND;
    const size_t outStride = (size_t)g2 * g2 * BOND;

    const int child = (2 * ny + (q >> 1)) * g + (2 * nx + (q & 1));
    const float* xin = in + (size_t)child * BOND;
    const float* fq  = f + (size_t)(node * 4 + q) * (BOND * RANK);
    float* Xq = Xt + q * 128 * XS;

    // --- prologue: kick F chunks 0,1 async, then stage X (plain, coalesced)
    {
        const float4* s4 = (const float4*)(fq);
        float4* d4 = (float4*)(Fs + q * CK * 64);
        for (int i = tg; i < CK * 16; i += 64) cp_async16(d4 + i, s4 + i);
        CP_COMMIT();
        const float4* s4b = (const float4*)(fq + CK * RANK);
        float4* d4b = (float4*)(Fs + 4096 + q * CK * 64);
        for (int i = tg; i < CK * 16; i += 64) cp_async16(d4b + i, s4b + i);
        CP_COMMIT();
    }
    for (int i = tg; i < TB * 128; i += 64) {
        int row = i >> 7, k = i & 127;
        Xq[k * XS + row] = xin[(size_t)(b0 + row) * inStride + k];
    }

    unsigned long long u2[8][2];
#pragma unroll
    for (int j = 0; j < 8; j++) { u2[j][0] = 0ULL; u2[j][1] = 0ULL; }

    for (int ch = 0; ch < NCH; ch++) {
        if (ch == NCH - 1) CP_WAIT0(); else CP_WAIT1();
        __syncthreads();

        const float* Fq = Fs + (ch & 1) * 4096 + q * CK * 64;
        const int c0 = ch * CK;
#pragma unroll 8
        for (int kk = 0; kk < CK; kk++) {
            ulonglong2 fv = *(const ulonglong2*)(Fq + kk * RANK + rg * 4);
            const float* xrow = Xq + (c0 + kk) * XS + bg * 8;
            float4 x0 = *(const float4*)(xrow);
            float4 x1 = *(const float4*)(xrow + 4);
            float a[8] = {x0.x, x0.y, x0.z, x0.w, x1.x, x1.y, x1.z, x1.w};
#pragma unroll
            for (int j = 0; j < 8; j++) {
                unsigned long long aa;
                BCAST2(aa, a[j]);
                FMA2(u2[j][0], aa, fv.x);
                FMA2(u2[j][1], aa, fv.y);
            }
        }
        __syncthreads();

        if (ch + 2 < NCH) {
            const float4* s4 = (const float4*)(fq + (ch + 2) * CK * RANK);
            float4* d4 = (float4*)(Fs + (ch & 1) * 4096 + q * CK * 64);
            for (int i = tg; i < CK * 16; i += 64) cp_async16(d4 + i, s4 + i);
            CP_COMMIT();
        }
    }

    // --- epilogue: async O prefetch, U write, P product, phase 2
    {
        const float4* ob4 = (const float4*)(o + (size_t)node * (RANK * BOND));
        float4* Os4 = (float4*)Os;
        for (int i = t; i < (RANK * BOND) / 4; i += 256)
            cp_async16(Os4 + i, ob4 + i);
        CP_COMMIT();
    }
    {
        float* Uq = Us + q * TB * 68;
#pragma unroll
        for (int j = 0; j < 8; j++) {
            unsigned v0, v1, v2, v3;
            UNPK2(v0, v1, u2[j][0]);
            UNPK2(v2, v3, u2[j][1]);
            float4 s;
            s.x = __uint_as_float(v0); s.y = __uint_as_float(v1);
            s.z = __uint_as_float(v2); s.w = __uint_as_float(v3);
            *(float4*)(Uq + (bg * 8 + j) * 68 + rg * 4) = s;
        }
    }
    __syncthreads();

    for (int idx = t; idx < TB * RANK; idx += 256) {
        int row = idx >> 6, r = idx & 63;
        Ps[row * 68 + r] = Us[0 * TB * 68 + row * 68 + r]
                         * Us[1 * TB * 68 + row * 68 + r]
                         * Us[2 * TB * 68 + row * 68 + r]
                         * Us[3 * TB * 68 + row * 68 + r];
    }
    CP_WAIT0();
    __syncthreads();

    // phase 2: out = P @ O (32 x 128), tile 2 rows x 8 cols
    const int bg2 = t >> 4;
    const int cg  = t & 15;
    unsigned long long acc2[2][4];
#pragma unroll
    for (int j = 0; j < 2; j++)
#pragma unroll
        for (int i = 0; i < 4; i++) acc2[j][i] = 0ULL;

#pragma unroll 8
    for (int r = 0; r < RANK; r++) {
        ulonglong2 w01 = *(const ulonglong2*)(Os + r * 128 + cg * 8);
        ulonglong2 w23 = *(const ulonglong2*)(Os + r * 128 + cg * 8 + 4);
        float a0 = Ps[(bg2 * 2)     * 68 + r];
        float a1 = Ps[(bg2 * 2 + 1) * 68 + r];
        unsigned long long aa0, aa1;
        BCAST2(aa0, a0);
        BCAST2(aa1, a1);
        FMA2(acc2[0][0], aa0, w01.x); FMA2(acc2[0][1], aa0, w01.y);
        FMA2(acc2[0][2], aa0, w23.x); FMA2(acc2[0][3], aa0, w23.y);
        FMA2(acc2[1][0], aa1, w01.x); FMA2(acc2[1][1], aa1, w01.y);
        FMA2(acc2[1][2], aa1, w23.x); FMA2(acc2[1][3], aa1, w23.y);
    }

#pragma unroll
    for (int j = 0; j < 2; j++) {
        int b = b0 + bg2 * 2 + j;
        float* op = out + (size_t)b * outStride + (size_t)node * BOND + cg * 8;
        unsigned v[8];
#pragma unroll
        for (int i = 0; i < 4; i++) UNPK2(v[2 * i], v[2 * i + 1], acc2[j][i]);
        float4 s0, s1;
        s0.x = __uint_as_float(v[0]); s0.y = __uint_as_float(v[1]);
        s0.z = __uint_as_float(v[2]); s0.w = __uint_as_float(v[3]);
        s1.x = __uint_as_float(v[4]); s1.y = __uint_as_float(v[5]);
        s1.z = __uint_as_float(v[6]); s1.w = __uint_as_float(v[7]);
        *(float4*)(op)     = s0;
        *(float4*)(op + 4) = s1;
    }
}

// ============================================================================
// K3: fused tail = L2 + L3 + LayerNorm + head GEMM + L2-normalize.
//   Block = 4 batches (grid 128). Weights read direct from gmem/L2 via __ldg.
// smem layout (floats):
//   Xs  [4 b][16 node][132]   @ 0      (8448)
//   X3  [4 b][4 node][132]    @ 8448   (2112)
//   Us  [4 q][4 b][68]        @ 10560  (1088)
//   Ps  [4 b][68]             @ 11648  (272)
//   hs  [4 b][132]            @ 11920  (528)
//   outs[4 b][512]            @ 12448  (2048)
//   stats (12)                @ 14496
// ============================================================================
#define TL_XS   0
#define TL_X3   8448
#define TL_US   10560
#define TL_PS   11648
#define TL_HS   11920
#define TL_OUT  12448
#define TL_ST   14496
#define TL_TOTAL (14496 + 16)

__global__ void __launch_bounds__(256)
tail_kernel(const float* __restrict__ f2, const float* __restrict__ o2,
            const float* __restrict__ f3, const float* __restrict__ o3,
            const float* __restrict__ gamma, const float* __restrict__ beta,
            const float* __restrict__ Wh,   const float* __restrict__ bh,
            float* __restrict__ outg)
{
    extern __shared__ float sm[];
    float* Xs = sm + TL_XS;
    float* X3 = sm + TL_X3;
    float* Us = sm + TL_US;
    float* Ps = sm + TL_PS;
    float* hs = sm + TL_HS;
    float* os = sm + TL_OUT;
    float* st = sm + TL_ST;     // mu[4], rs[4], rn[4]

    const int t    = threadIdx.x;
    const int b0   = blockIdx.x * 4;
    const int q    = t >> 6;
    const int tg   = t & 63;
    const int bq   = tg >> 4;          // batch for U phases
    const int rg   = tg & 15;          // ranks rg*4..+3
    const int bo   = t >> 6;           // batch for GEMM phases
    const int c0   = (t & 63) * 2;     // 2 cols per thread in O-GEMMs
    const int lane = t & 31;
    const int w    = t >> 5;

    // stage h2 slice: [4 b][16 node][128] (coalesced on k)
    for (int i = t; i < 4 * 16 * 128; i += 256) {
        int b = i >> 11, rem = i & 2047;
        int n = rem >> 7, k = rem & 127;
        Xs[b * 2112 + n * 132 + k] = g_h2[(size_t)(b0 + b) * (16 * BOND) + n * BOND + k];
    }
    __syncthreads();

    // ---------------- Level 2: 4 out-nodes ----------------
    for (int n = 0; n < 4; n++) {
        const int child = (2 * (n >> 1) + (q >> 1)) * 4 + 2 * (n & 1) + (q & 1);
        const float* fp = f2 + (size_t)(n * 4 + q) * (BOND * RANK) + rg * 4;
        const float* xp = Xs + bq * 2112 + child * 132;

        unsigned long long u2[2] = {0ULL, 0ULL};
#pragma unroll 8
        for (int k = 0; k < 128; k++) {
            ulonglong2 fv = __ldg((const ulonglong2*)(fp + (size_t)k * RANK));
            unsigned long long aa;
            BCAST2(aa, xp[k]);
            FMA2(u2[0], aa, fv.x);
            FMA2(u2[1], aa, fv.y);
        }
        {
            unsigned v0, v1, v2, v3;
            UNPK2(v0, v1, u2[0]); UNPK2(v2, v3, u2[1]);
            float4 s;
            s.x = __uint_as_float(v0); s.y = __uint_as_float(v1);
            s.z = __uint_as_float(v2); s.w = __uint_as_float(v3);
            *(float4*)(Us + q * (4 * 68) + bq * 68 + rg * 4) = s;
        }
        __syncthreads();
        {   // P product: 4b x 64r = 256 = one elem/thread
            int b = t >> 6, r = t & 63;
            Ps[b * 68 + r] = Us[0 * 272 + b * 68 + r] * Us[1 * 272 + b * 68 + r]
                           * Us[2 * 272 + b * 68 + r] * Us[3 * 272 + b * 68 + r];
        }
        __syncthreads();
        {   // out3[b][n][c] = P @ O2[n]
            unsigned long long acc = 0ULL;
            const float* op = o2 + (size_t)n * (RANK * BOND) + c0;
#pragma unroll 8
            for (int r = 0; r < RANK; r++) {
                unsigned long long wv = __ldg((const unsigned long long*)(op + (size_t)r * BOND));
                unsigned long long aa;
                BCAST2(aa, Ps[bo * 68 + r]);
                FMA2(acc, aa, wv);
            }
            unsigned vlo, vhi; UNPK2(vlo, vhi, acc);
            X3[bo * 528 + n * 132 + c0]     = __uint_as_float(vlo);
            X3[bo * 528 + n * 132 + c0 + 1] = __uint_as_float(vhi);
        }
        __syncthreads();
    }

    // ---------------- Level 3: single node, children = nodes 0..3 ----------
    {
        const float* fp = f3 + (size_t)q * (BOND * RANK) + rg * 4;
        const float* xp = X3 + bq * 528 + q * 132;

        unsigned long long u2[2] = {0ULL, 0ULL};
#pragma unroll 8
        for (int k = 0; k < 128; k++) {
            ulonglong2 fv = __ldg((const ulonglong2*)(fp + (size_t)k * RANK));
            unsigned long long aa;
            BCAST2(aa, xp[k]);
            FMA2(u2[0], aa, fv.x);
            FMA2(u2[1], aa, fv.y);
        }
        {
            unsigned v0, v1, v2, v3;
            UNPK2(v0, v1, u2[0]); UNPK2(v2, v3, u2[1]);
            float4 s;
            s.x = __uint_as_float(v0); s.y = __uint_as_float(v1);
            s.z = __uint_as_float(v2); s.w = __uint_as_float(v3);
            *(float4*)(Us + q * 272 + bq * 68 + rg * 4) = s;
        }
        __syncthreads();
        {
            int b = t >> 6, r = t & 63;
            Ps[b * 68 + r] = Us[0 * 272 + b * 68 + r] * Us[1 * 272 + b * 68 + r]
                           * Us[2 * 272 + b * 68 + r] * Us[3 * 272 + b * 68 + r];
        }
        __syncthreads();
        {
            unsigned long long acc = 0ULL;
            const float* op = o3 + c0;
#pragma unroll 8
            for (int r = 0; r < RANK; r++) {
                unsigned long long wv = __ldg((const unsigned long long*)(op + (size_t)r * BOND));
                unsigned long long aa;
                BCAST2(aa, Ps[bo * 68 + r]);
                FMA2(acc, aa, wv);
            }
            unsigned vlo, vhi; UNPK2(vlo, vhi, acc);
            hs[bo * 132 + c0]     = __uint_as_float(vlo);
            hs[bo * 132 + c0 + 1] = __uint_as_float(vhi);
        }
        __syncthreads();
    }

    // ---------------- LayerNorm ----------------
    if (w < 4) {
        float s = 0.f, ss = 0.f;
        for (int c = lane; c < BOND; c += 32) {
            float v = hs[w * 132 + c]; s += v; ss += v * v;
        }
#pragma unroll
        for (int off = 16; off; off >>= 1) {
            s  += __shfl_xor_sync(0xffffffffu, s, off);
            ss += __shfl_xor_sync(0xffffffffu, ss, off);
        }
        if (lane == 0) {
            float mu = s * (1.f / BOND);
            st[w] = mu;
            st[4 + w] = rsqrtf(ss * (1.f / BOND) - mu * mu + 1e-5f);
        }
    }
    __syncthreads();
    for (int i = t; i < 4 * BOND; i += 256) {
        int b = i >> 7, c = i & 127;
        hs[b * 132 + c] = (hs[b * 132 + c] - st[b]) * st[4 + b]
                          * __ldg(gamma + c) + __ldg(beta + c);
    }
    __syncthreads();

    // ---------------- head GEMM: 4 x 512, thread = 2 cols ----------------
    {
        const int e = t * 2;
        unsigned long long acc[4];
        unsigned long long binit;
        PACK2(binit, __ldg(bh + e), __ldg(bh + e + 1));
#pragma unroll
        for (int b = 0; b < 4; b++) acc[b] = binit;

#pragma unroll 8
        for (int c = 0; c < BOND; c++) {
            unsigned long long wv = __ldg((const unsigned long long*)(Wh + (size_t)c * EMB + e));
#pragma unroll
            for (int b = 0; b < 4; b++) {
                unsigned long long aa;
                BCAST2(aa, hs[b * 132 + c]);
                FMA2(acc[b], aa, wv);
            }
        }
#pragma unroll
        for (int b = 0; b < 4; b++) {
            unsigned vlo, vhi; UNPK2(vlo, vhi, acc[b]);
            os[b * 512 + e]     = __uint_as_float(vlo);
            os[b * 512 + e + 1] = __uint_as_float(vhi);
        }
    }
    __syncthreads();

    // ---------------- L2 norm + store ----------------
    if (w < 4) {
        float ss = 0.f;
        for (int e = lane; e < EMB; e += 32) {
            float v = os[w * 512 + e]; ss += v * v;
        }
#pragma unroll
        for (int off = 16; off; off >>= 1)
            ss += __shfl_xor_sync(0xffffffffu, ss, off);
        if (lane == 0)
            st[8 + w] = 1.f / fmaxf(sqrtf(ss), 1e-12f);
    }
    __syncthreads();
    for (int i = t; i < 4 * EMB; i += 256) {
        int b = i >> 9, e = i & 511;
        outg[(size_t)(b0 + b) * EMB + e] = os[b * 512 + e] * st[8 + b];
    }
}

// ============================================================================
// launch
// ============================================================================
extern "C" void kernel_launch(void* const* d_in, const int* in_sizes, int n_in,
                              void* d_out, int out_size)
{
    const float *x, *Wp, *bp, *pos, *gamma, *beta, *Wh, *bh;
    const float *f0, *o0, *f1, *o1, *f2, *o2, *f3, *o3;

    x   = (const float*)d_in[0];
    Wp  = (const float*)d_in[1];
    bp  = (const float*)d_in[2];
    pos = (const float*)d_in[3];
    if (in_sizes[4] == BOND) {          // setup_inputs() dict order
        gamma = (const float*)d_in[4];  beta = (const float*)d_in[5];
        Wh    = (const float*)d_in[6];  bh   = (const float*)d_in[7];
        f0 = (const float*)d_in[8];   o0 = (const float*)d_in[9];
        f1 = (const float*)d_in[10];  o1 = (const float*)d_in[11];
        f2 = (const float*)d_in[12];  o2 = (const float*)d_in[13];
        f3 = (const float*)d_in[14];  o3 = (const float*)d_in[15];
    } else {                            // reference-signature order fallback
        f0 = (const float*)d_in[4];   o0 = (const float*)d_in[5];
        f1 = (const float*)d_in[6];   o1 = (const float*)d_in[7];
        f2 = (const float*)d_in[8];   o2 = (const float*)d_in[9];
        f3 = (const float*)d_in[10];  o3 = (const float*)d_in[11];
        gamma = (const float*)d_in[12]; beta = (const float*)d_in[13];
        Wh    = (const float*)d_in[14]; bh   = (const float*)d_in[15];
    }
    float* outp = (float*)d_out;

    const int SM_K1   = (64 * 132 + 64 * 128) * (int)sizeof(float);        // 66560
    const int SM_CP   = (4 * 128 * 36 + 2 * 4096) * (int)sizeof(float);    // 106496
    const int SM_TAIL = TL_TOTAL * (int)sizeof(float);                     // ~58 KB

    cudaFuncSetAttribute((const void*)patch_embed_kernel,
                         cudaFuncAttributeMaxDynamicSharedMemorySize, SM_K1);
    cudaFuncSetAttribute((const void*)cp_level_v4,
                         cudaFuncAttributeMaxDynamicSharedMemorySize, SM_CP);
    cudaFuncSetAttribute((const void*)tail_kernel,
                         cudaFuncAttributeMaxDynamicSharedMemorySize, SM_TAIL);

    float *h0, *h1, *h2;
    cudaGetSymbolAddress((void**)&h0, g_h0);
    cudaGetSymbolAddress((void**)&h1, g_h1);
    cudaGetSymbolAddress((void**)&h2, g_h2);

    patch_embed_kernel<<<1024, 256, SM_K1>>>(x, Wp, bp, pos);

    cp_level_v4<<<dim3(BATCH / 32, 64), 256, SM_CP>>>(h0, h1, f0, o0, 16);
    cp_level_v4<<<dim3(BATCH / 32, 16), 256, SM_CP>>>(h1, h2, f1, o1, 8);

    tail_kernel<<<BATCH / 4, 256, SM_TAIL>>>(f2, o2, f3, o3,
                                             gamma, beta, Wh, bh, outp);
}

// round 17
// speedup vs baseline: 1.3507x; 1.3507x over previous
#include <cuda_runtime.h>
#include <cstdint>

#define BATCH     512
#define NP        256
#define BOND      128
#define RANK      64
#define EMB       512

// packed fp32x2 helpers ------------------------------------------------------
#define FMA2(d, a, b) \
    asm("fma.rn.f32x2 %0, %1, %2, %0;" : "+l"(d) : "l"(a), "l"(b))
#define BCAST2(d, s) \
    asm("mov.b64 %0, {%1, %1};" : "=l"(d) : "r"(__float_as_uint(s)))
#define UNPK2(lo, hi, s) \
    asm("mov.b64 {%0, %1}, %2;" : "=r"(lo), "=r"(hi) : "l"(s))

// cp.async helpers -----------------------------------------------------------
__device__ __forceinline__ void cp_async16(void* dst, const void* src) {
    unsigned sa = (unsigned)__cvta_generic_to_shared(dst);
    asm volatile("cp.async.ca.shared.global [%0], [%1], 16;\n" :: "r"(sa), "l"(src));
}
#define CP_COMMIT() asm volatile("cp.async.commit_group;\n" ::: "memory")
#define CP_WAIT0()  asm volatile("cp.async.wait_group 0;\n" ::: "memory")
#define CP_WAIT1()  asm volatile("cp.async.wait_group 1;\n" ::: "memory")

// ---------------- scratch (static device globals: allocation-free) ----------
__device__ float g_h0[BATCH * NP * BOND];   // 67 MB
__device__ float g_h1[BATCH * 64 * BOND];
__device__ float g_h2[BATCH * 16 * BOND];
__device__ float g_h3[BATCH * 4  * BOND];
__device__ float g_h4[BATCH * 1  * BOND];

// ============================================================================
// K1: patchify + patch GEMM + bias + pos (unchanged, passing)
// ============================================================================
__global__ void __launch_bounds__(256)
patch_embed_kernel(const float* __restrict__ x,
                   const float* __restrict__ Wp,
                   const float* __restrict__ bp,
                   const float* __restrict__ pos)
{
    extern __shared__ float sm[];
    float* At = sm;                 // [64][132]  (k-major)
    float* Ws = sm + 64 * 132;      // [64][128]

    const int tid = threadIdx.x;
    const int r0  = blockIdx.x * 128;

    for (int idx = tid; idx < 128 * 64; idx += 256) {
        int i = idx >> 6;
        int k = idx & 63;
        int row = r0 + i;
        int b = row >> 8, p = row & 255;
        int gy = p >> 4, gx = p & 15;
        int py = k >> 3, px = k & 7;
        At[k * 132 + i] = x[(b * 128 + gy * 8 + py) * 128 + gx * 8 + px];
    }
    for (int idx = tid; idx < 64 * 128; idx += 256)
        Ws[idx] = Wp[idx];
    __syncthreads();

    const int rg = tid >> 4;
    const int cg = tid & 15;

    unsigned long long acc2[8][4];
#pragma unroll
    for (int j = 0; j < 8; j++)
#pragma unroll
        for (int i = 0; i < 4; i++) acc2[j][i] = 0ULL;

#pragma unroll 4
    for (int k = 0; k < 64; k++) {
        ulonglong2 w01 = *(const ulonglong2*)(Ws + k * 128 + cg * 8);
        ulonglong2 w23 = *(const ulonglong2*)(Ws + k * 128 + cg * 8 + 4);
        float4 a0 = *(const float4*)(At + k * 132 + rg * 8);
        float4 a1 = *(const float4*)(At + k * 132 + rg * 8 + 4);
        float a[8] = {a0.x, a0.y, a0.z, a0.w, a1.x, a1.y, a1.z, a1.w};
#pragma unroll
        for (int j = 0; j < 8; j++) {
            unsigned long long aa;
            BCAST2(aa, a[j]);
            FMA2(acc2[j][0], aa, w01.x);
            FMA2(acc2[j][1], aa, w01.y);
            FMA2(acc2[j][2], aa, w23.x);
            FMA2(acc2[j][3], aa, w23.y);
        }
    }

    float4 bp0 = *(const float4*)(bp + cg * 8);
    float4 bp1 = *(const float4*)(bp + cg * 8 + 4);
#pragma unroll
    for (int j = 0; j < 8; j++) {
        int row = r0 + rg * 8 + j;
        int p = row & 255;
        float4 p0 = *(const float4*)(pos + p * 128 + cg * 8);
        float4 p1 = *(const float4*)(pos + p * 128 + cg * 8 + 4);
        unsigned v[8];
#pragma unroll
        for (int i = 0; i < 4; i++) UNPK2(v[2 * i], v[2 * i + 1], acc2[j][i]);
        float4 o0, o1;
        o0.x = __uint_as_float(v[0]) + bp0.x + p0.x;
        o0.y = __uint_as_float(v[1]) + bp0.y + p0.y;
        o0.z = __uint_as_float(v[2]) + bp0.z + p0.z;
        o0.w = __uint_as_float(v[3]) + bp0.w + p0.w;
        o1.x = __uint_as_float(v[4]) + bp1.x + p1.x;
        o1.y = __uint_as_float(v[5]) + bp1.y + p1.y;
        o1.z = __uint_as_float(v[6]) + bp1.z + p1.z;
        o1.w = __uint_as_float(v[7]) + bp1.w + p1.w;
        *(float4*)(g_h0 + (size_t)row * 128 + cg * 8)     = o0;
        *(float4*)(g_h0 + (size_t)row * 128 + cg * 8 + 4) = o1;
    }
}

// ============================================================================
// K2 v4: CP level, ALL levels (TB=32 batches/block).
//   cp.async double-buffered F (CK=16), async O prefetch under the epilogue.
//   grid = (BATCH/32, out_nodes)
// ============================================================================
__global__ void __launch_bounds__(256)
cp_level_v4(const float* __restrict__ in,
            float* __restrict__ out,
            const float* __restrict__ f,
            const float* __restrict__ o,
            int g)
{
    constexpr int TB = 32;
    constexpr int XS = 36;           // Xt row stride (mult of 4)
    constexpr int CK = 16;           // F k-chunk
    constexpr int NCH = 128 / CK;    // 8 chunks

    extern __shared__ float sm[];
    float* Xt = sm;                        // [4][128][36] = 18432 floats
    float* Fs = sm + 4 * 128 * XS;         // [2][4][CK][64] = 8192 floats
    float* Us = sm;                        // alias Xt: [4][32][68] = 8704
    float* Ps = sm + 4 * TB * 68;          // alias Xt+8704: [32][68] = 2176
    float* Os = Fs;                        // alias Fs: [64][128] = 8192 floats

    const int t  = threadIdx.x;
    const int q  = t >> 6;
    const int tg = t & 63;
    const int bg = tg >> 4;          // 0..3 -> rows bg*8..
    const int rg = tg & 15;          // ranks rg*4..+3

    const int node = blockIdx.y;
    const int b0   = blockIdx.x * TB;
    const int g2   = g >> 1;
    const int ny   = node / g2, nx = node % g2;
    const size_t inStride  = (size_t)g * g * BOND;
    const size_t outStride = (size_t)g2 * g2 * BOND;

    const int child = (2 * ny + (q >> 1)) * g + (2 * nx + (q & 1));
    const float* xin = in + (size_t)child * BOND;
    const float* fq  = f + (size_t)(node * 4 + q) * (BOND * RANK);
    float* Xq = Xt + q * 128 * XS;

    // --- prologue: kick F chunks 0,1 async, then stage X (plain, coalesced)
    {
        const float4* s4 = (const float4*)(fq);
        float4* d4 = (float4*)(Fs + q * CK * 64);
        for (int i = tg; i < CK * 16; i += 64) cp_async16(d4 + i, s4 + i);
        CP_COMMIT();
        const float4* s4b = (const float4*)(fq + CK * RANK);
        float4* d4b = (float4*)(Fs + 4096 + q * CK * 64);
        for (int i = tg; i < CK * 16; i += 64) cp_async16(d4b + i, s4b + i);
        CP_COMMIT();
    }
    for (int i = tg; i < TB * 128; i += 64) {
        int row = i >> 7, k = i & 127;
        Xq[k * XS + row] = xin[(size_t)(b0 + row) * inStride + k];
    }

    unsigned long long u2[8][2];
#pragma unroll
    for (int j = 0; j < 8; j++) { u2[j][0] = 0ULL; u2[j][1] = 0ULL; }

    for (int ch = 0; ch < NCH; ch++) {
        if (ch == NCH - 1) CP_WAIT0(); else CP_WAIT1();
        __syncthreads();

        const float* Fq = Fs + (ch & 1) * 4096 + q * CK * 64;
        const int c0 = ch * CK;
#pragma unroll 8
        for (int kk = 0; kk < CK; kk++) {
            ulonglong2 fv = *(const ulonglong2*)(Fq + kk * RANK + rg * 4);
            const float* xrow = Xq + (c0 + kk) * XS + bg * 8;
            float4 x0 = *(const float4*)(xrow);
            float4 x1 = *(const float4*)(xrow + 4);
            float a[8] = {x0.x, x0.y, x0.z, x0.w, x1.x, x1.y, x1.z, x1.w};
#pragma unroll
            for (int j = 0; j < 8; j++) {
                unsigned long long aa;
                BCAST2(aa, a[j]);
                FMA2(u2[j][0], aa, fv.x);
                FMA2(u2[j][1], aa, fv.y);
            }
        }
        __syncthreads();

        if (ch + 2 < NCH) {
            const float4* s4 = (const float4*)(fq + (ch + 2) * CK * RANK);
            float4* d4 = (float4*)(Fs + (ch & 1) * 4096 + q * CK * 64);
            for (int i = tg; i < CK * 16; i += 64) cp_async16(d4 + i, s4 + i);
            CP_COMMIT();
        }
    }

    // --- epilogue: async O prefetch, U write, P product, phase 2
    {
        const float4* ob4 = (const float4*)(o + (size_t)node * (RANK * BOND));
        float4* Os4 = (float4*)Os;
        for (int i = t; i < (RANK * BOND) / 4; i += 256)
            cp_async16(Os4 + i, ob4 + i);
        CP_COMMIT();
    }
    {
        float* Uq = Us + q * TB * 68;
#pragma unroll
        for (int j = 0; j < 8; j++) {
            unsigned v0, v1, v2, v3;
            UNPK2(v0, v1, u2[j][0]);
            UNPK2(v2, v3, u2[j][1]);
            float4 s;
            s.x = __uint_as_float(v0); s.y = __uint_as_float(v1);
            s.z = __uint_as_float(v2); s.w = __uint_as_float(v3);
            *(float4*)(Uq + (bg * 8 + j) * 68 + rg * 4) = s;
        }
    }
    __syncthreads();

    for (int idx = t; idx < TB * RANK; idx += 256) {
        int row = idx >> 6, r = idx & 63;
        Ps[row * 68 + r] = Us[0 * TB * 68 + row * 68 + r]
                         * Us[1 * TB * 68 + row * 68 + r]
                         * Us[2 * TB * 68 + row * 68 + r]
                         * Us[3 * TB * 68 + row * 68 + r];
    }
    CP_WAIT0();
    __syncthreads();

    // phase 2: out = P @ O (32 x 128), tile 2 rows x 8 cols
    const int bg2 = t >> 4;
    const int cg  = t & 15;
    unsigned long long acc2[2][4];
#pragma unroll
    for (int j = 0; j < 2; j++)
#pragma unroll
        for (int i = 0; i < 4; i++) acc2[j][i] = 0ULL;

#pragma unroll 8
    for (int r = 0; r < RANK; r++) {
        ulonglong2 w01 = *(const ulonglong2*)(Os + r * 128 + cg * 8);
        ulonglong2 w23 = *(const ulonglong2*)(Os + r * 128 + cg * 8 + 4);
        float a0 = Ps[(bg2 * 2)     * 68 + r];
        float a1 = Ps[(bg2 * 2 + 1) * 68 + r];
        unsigned long long aa0, aa1;
        BCAST2(aa0, a0);
        BCAST2(aa1, a1);
        FMA2(acc2[0][0], aa0, w01.x); FMA2(acc2[0][1], aa0, w01.y);
        FMA2(acc2[0][2], aa0, w23.x); FMA2(acc2[0][3], aa0, w23.y);
        FMA2(acc2[1][0], aa1, w01.x); FMA2(acc2[1][1], aa1, w01.y);
        FMA2(acc2[1][2], aa1, w23.x); FMA2(acc2[1][3], aa1, w23.y);
    }

#pragma unroll
    for (int j = 0; j < 2; j++) {
        int b = b0 + bg2 * 2 + j;
        float* op = out + (size_t)b * outStride + (size_t)node * BOND + cg * 8;
        unsigned v[8];
#pragma unroll
        for (int i = 0; i < 4; i++) UNPK2(v[2 * i], v[2 * i + 1], acc2[j][i]);
        float4 s0, s1;
        s0.x = __uint_as_float(v[0]); s0.y = __uint_as_float(v[1]);
        s0.z = __uint_as_float(v[2]); s0.w = __uint_as_float(v[3]);
        s1.x = __uint_as_float(v[4]); s1.y = __uint_as_float(v[5]);
        s1.z = __uint_as_float(v[6]); s1.w = __uint_as_float(v[7]);
        *(float4*)(op)     = s0;
        *(float4*)(op + 4) = s1;
    }
}

// ============================================================================
// K3: LayerNorm + head GEMM + row L2-normalize (R15 version, smem-staged Wh
//   via broadcast reads; 8 batches/block, 64 blocks)
// ============================================================================
__global__ void __launch_bounds__(512)
head_kernel(const float* __restrict__ gamma,
            const float* __restrict__ beta,
            const float* __restrict__ Wh,
            const float* __restrict__ bh,
            float* __restrict__ outg)
{
    constexpr int BB = 8;
    __shared__ float hs[BB][BOND];
    __shared__ float outs[BB][EMB];
    __shared__ float mu_s[BB], rs_s[BB], rn_s[BB];

    const int tid = threadIdx.x;
    const int b0  = blockIdx.x * BB;
    const int w   = tid >> 5, lane = tid & 31;

    for (int idx = tid; idx < BB * BOND; idx += 512)
        hs[idx >> 7][idx & 127] = g_h4[(size_t)(b0 + (idx >> 7)) * BOND + (idx & 127)];
    __syncthreads();

    if (w < BB) {
        float s = 0.f, ss = 0.f;
        for (int c = lane; c < BOND; c += 32) {
            float v = hs[w][c]; s += v; ss += v * v;
        }
#pragma unroll
        for (int off = 16; off; off >>= 1) {
            s  += __shfl_xor_sync(0xffffffffu, s, off);
            ss += __shfl_xor_sync(0xffffffffu, ss, off);
        }
        if (lane == 0) {
            float mu = s * (1.f / BOND);
            mu_s[w] = mu;
            rs_s[w] = rsqrtf(ss * (1.f / BOND) - mu * mu + 1e-5f);
        }
    }
    __syncthreads();

    for (int idx = tid; idx < BB * BOND; idx += 512) {
        int bb = idx >> 7, c = idx & 127;
        hs[bb][c] = (hs[bb][c] - mu_s[bb]) * rs_s[bb] * gamma[c] + beta[c];
    }
    __syncthreads();

    const int e = tid;
    float acc[BB];
    float bhe = bh[e];
#pragma unroll
    for (int j = 0; j < BB; j++) acc[j] = bhe;

#pragma unroll 8
    for (int c = 0; c < BOND; c++) {
        float wv = Wh[(size_t)c * EMB + e];
#pragma unroll
        for (int j = 0; j < BB; j++) acc[j] += hs[j][c] * wv;
    }
#pragma unroll
    for (int j = 0; j < BB; j++) outs[j][e] = acc[j];
    __syncthreads();

    if (w < BB) {
        float ss = 0.f;
        for (int ee = lane; ee < EMB; ee += 32) {
            float v = outs[w][ee]; ss += v * v;
        }
#pragma unroll
        for (int off = 16; off; off >>= 1)
            ss += __shfl_xor_sync(0xffffffffu, ss, off);
        if (lane == 0)
            rn_s[w] = 1.f / fmaxf(sqrtf(ss), 1e-12f);
    }
    __syncthreads();

    for (int idx = tid; idx < BB * EMB; idx += 512) {
        int bb = idx >> 9, ee = idx & 511;
        outg[(size_t)(b0 + bb) * EMB + ee] = outs[bb][ee] * rn_s[bb];
    }
}

// ============================================================================
// launch
// ============================================================================
extern "C" void kernel_launch(void* const* d_in, const int* in_sizes, int n_in,
                              void* d_out, int out_size)
{
    const float *x, *Wp, *bp, *pos, *gamma, *beta, *Wh, *bh;
    const float *f0, *o0, *f1, *o1, *f2, *o2, *f3, *o3;

    x   = (const float*)d_in[0];
    Wp  = (const float*)d_in[1];
    bp  = (const float*)d_in[2];
    pos = (const float*)d_in[3];
    if (in_sizes[4] == BOND) {          // setup_inputs() dict order
        gamma = (const float*)d_in[4];  beta = (const float*)d_in[5];
        Wh    = (const float*)d_in[6];  bh   = (const float*)d_in[7];
        f0 = (const float*)d_in[8];   o0 = (const float*)d_in[9];
        f1 = (const float*)d_in[10];  o1 = (const float*)d_in[11];
        f2 = (const float*)d_in[12];  o2 = (const float*)d_in[13];
        f3 = (const float*)d_in[14];  o3 = (const float*)d_in[15];
    } else {                            // reference-signature order fallback
        f0 = (const float*)d_in[4];   o0 = (const float*)d_in[5];
        f1 = (const float*)d_in[6];   o1 = (const float*)d_in[7];
        f2 = (const float*)d_in[8];   o2 = (const float*)d_in[9];
        f3 = (const float*)d_in[10];  o3 = (const float*)d_in[11];
        gamma = (const float*)d_in[12]; beta = (const float*)d_in[13];
        Wh    = (const float*)d_in[14]; bh   = (const float*)d_in[15];
    }
    float* outp = (float*)d_out;

    const int SM_K1 = (64 * 132 + 64 * 128) * (int)sizeof(float);      // 66560
    const int SM_CP = (4 * 128 * 36 + 2 * 4096) * (int)sizeof(float);  // 106496

    cudaFuncSetAttribute((const void*)patch_embed_kernel,
                         cudaFuncAttributeMaxDynamicSharedMemorySize, SM_K1);
    cudaFuncSetAttribute((const void*)cp_level_v4,
                         cudaFuncAttributeMaxDynamicSharedMemorySize, SM_CP);

    float *h0, *h1, *h2, *h3, *h4;
    cudaGetSymbolAddress((void**)&h0, g_h0);
    cudaGetSymbolAddress((void**)&h1, g_h1);
    cudaGetSymbolAddress((void**)&h2, g_h2);
    cudaGetSymbolAddress((void**)&h3, g_h3);
    cudaGetSymbolAddress((void**)&h4, g_h4);

    patch_embed_kernel<<<1024, 256, SM_K1>>>(x, Wp, bp, pos);

    cp_level_v4<<<dim3(BATCH / 32, 64), 256, SM_CP>>>(h0, h1, f0, o0, 16);
    cp_level_v4<<<dim3(BATCH / 32, 16), 256, SM_CP>>>(h1, h2, f1, o1, 8);
    cp_level_v4<<<dim3(BATCH / 32, 4),  256, SM_CP>>>(h2, h3, f2, o2, 4);
    cp_level_v4<<<dim3(BATCH / 32, 1),  256, SM_CP>>>(h3, h4, f3, o3, 2);

    head_kernel<<<BATCH / 8, 512>>>(gamma, beta, Wh, bh, outp);
}